// round 16
// baseline (speedup 1.0000x reference)
#include <cuda_runtime.h>
#include <cuda_bf16.h>
#include <cstdint>

typedef unsigned long long ull;

// ---------------- f32x2 packed helpers (Blackwell) ----------------
__device__ __forceinline__ ull ffma2(ull a, ull b, ull c) {
    ull d;
    asm("fma.rn.f32x2 %0, %1, %2, %3;" : "=l"(d) : "l"(a), "l"(b), "l"(c));
    return d;
}
__device__ __forceinline__ ull pack2(float lo, float hi) {
    ull r;
    asm("mov.b64 %0, {%1, %2};" : "=l"(r) : "f"(lo), "f"(hi));
    return r;
}
__device__ __forceinline__ void unpack2(ull v, float& lo, float& hi) {
    asm("mov.b64 {%0, %1}, %2;" : "=f"(lo), "=f"(hi) : "l"(v));
}
__device__ __forceinline__ ull relu2(ull v) {
    float lo, hi;
    unpack2(v, lo, hi);
    return pack2(fmaxf(lo, 0.0f), fmaxf(hi, 0.0f));
}

static constexpr int C = 16;
static constexpr int TPB = 128;               // 128 threads * 4 rows = 512-row tile
static constexpr int ROWS = 4;                // rows per thread (amortize LDC)
static constexpr int TILE_ROWS = TPB * ROWS;  // 512
static constexpr int TILE_F4 = TILE_ROWS * 4; // 2048 float4 = 32KB

// Swizzle on float4 index: XOR low 3 bits with bits [4:7).
// Conflict-free for both the coalesced k*TPB+tid pattern and 16*tid+j.
__device__ __forceinline__ int sw(int L) { return L ^ ((L >> 4) & 7); }

// Folded parameters in __constant__ -> weight reads on the constant port.
struct FoldedParams {
    float WcT[C * C];   // [i*16 + o]   Wc^T, o contiguous (pairs adjacent)
    float WbT[C * C];   // [o*16 + q]   Wb^T, q contiguous
    float bc[C];        // folded bias: Wa@bt + ba
    float bb[C];
};

__device__ FoldedParams gStage;
__constant__ __align__(16) FoldedParams cP;

__global__ void fold_kernel(const float* __restrict__ Wt,
                            const float* __restrict__ bt,
                            const float* __restrict__ Wa,
                            const float* __restrict__ ba,
                            const float* __restrict__ Wb,
                            const float* __restrict__ bb)
{
    const int t = threadIdx.x;           // 256 threads
    const int o = t & 15;
    const int i = t >> 4;
    float acc = 0.0f;
#pragma unroll
    for (int m = 0; m < C; m++)
        acc += Wa[o * C + m] * Wt[m * C + i];
    gStage.WcT[i * C + o] = acc;
    gStage.WbT[t] = Wb[(t & 15) * C + (t >> 4)];
    if (t < C) {
        float b = ba[t];
#pragma unroll
        for (int m = 0; m < C; m++)
            b += Wa[t * C + m] * bt[m];
        gStage.bc[t] = b;
        gStage.bb[t] = bb[t];
    }
}

__global__ __launch_bounds__(TPB, 5)
void dmasif_fused_kernel(const float* __restrict__ feat,
                         float* __restrict__ out,
                         long long n)
{
    __shared__ float4 sT[TILE_F4];    // 32KB, features then reused for outputs

    const int tid = threadIdx.x;
    const long long tileBase = (long long)blockIdx.x * TILE_ROWS;
    const bool fullTile = (tileBase + TILE_ROWS <= n);

    if (!fullTile) {
        // ---------- partial-tile path (last block only; dead for N%512==0) ----------
        const long long base = tileBase + (long long)tid * ROWS;
        if (base >= n) return;
        for (int r = 0; r < ROWS; r++) {
            const long long row = base + r;
            if (row >= n) break;
            float h[C];
#pragma unroll
            for (int q = 0; q < C; q++) {
                float a = cP.bc[q];
                for (int i = 0; i < C; i++)
                    a += feat[row * C + i] * cP.WcT[i * C + q];
                h[q] = fmaxf(a, 0.0f);
            }
#pragma unroll
            for (int q = 0; q < C; q++) {
                float a = cP.bb[q];
                for (int o = 0; o < C; o++)
                    a += h[o] * cP.WbT[o * C + q];
                out[row * C + q] = a;
            }
        }
        return;
    }

    // ================= full tile =================
    // 1) coalesced load -> swizzled smem  (16 x float4 per thread)
    {
        const float4* gf4 = reinterpret_cast<const float4*>(feat + tileBase * C);
#pragma unroll
        for (int k = 0; k < 16; k++) {
            const int L = k * TPB + tid;
            sT[sw(L)] = gf4[L];
        }
    }
    __syncthreads();

    // ---- GEMM1 + ReLU: acc[r][p] = (h[r][2p], h[r][2p+1]) ----
    // Feature float4s read from smem PER ic-CHUNK (4 live at a time).
    ull acc[ROWS][8];
#pragma unroll
    for (int p = 0; p < 8; p++) {
        const ull bp = *reinterpret_cast<const ull*>(&cP.bc[2 * p]);
#pragma unroll
        for (int r = 0; r < ROWS; r++) acc[r][p] = bp;
    }

#pragma unroll
    for (int ic = 0; ic < 4; ic++) {
        const float4 g0 = sT[sw(16 * tid + 0 * 4 + ic)];
        const float4 g1 = sT[sw(16 * tid + 1 * 4 + ic)];
        const float4 g2 = sT[sw(16 * tid + 2 * 4 + ic)];
        const float4 g3 = sT[sw(16 * tid + 3 * 4 + ic)];
        float e0v[4] = {g0.x, g0.y, g0.z, g0.w};
        float e1v[4] = {g1.x, g1.y, g1.z, g1.w};
        float e2v[4] = {g2.x, g2.y, g2.z, g2.w};
        float e3v[4] = {g3.x, g3.y, g3.z, g3.w};
#pragma unroll
        for (int ii = 0; ii < 4; ii++) {
            const int i = ic * 4 + ii;
            const ulonglong2 wA = *reinterpret_cast<const ulonglong2*>(&cP.WcT[i * C + 0]);
            const ulonglong2 wB = *reinterpret_cast<const ulonglong2*>(&cP.WcT[i * C + 4]);
            const ulonglong2 wC = *reinterpret_cast<const ulonglong2*>(&cP.WcT[i * C + 8]);
            const ulonglong2 wD = *reinterpret_cast<const ulonglong2*>(&cP.WcT[i * C + 12]);
            const ull d0 = pack2(e0v[ii], e0v[ii]);
            const ull d1 = pack2(e1v[ii], e1v[ii]);
            const ull d2 = pack2(e2v[ii], e2v[ii]);
            const ull d3 = pack2(e3v[ii], e3v[ii]);
            acc[0][0] = ffma2(d0, wA.x, acc[0][0]); acc[0][1] = ffma2(d0, wA.y, acc[0][1]);
            acc[0][2] = ffma2(d0, wB.x, acc[0][2]); acc[0][3] = ffma2(d0, wB.y, acc[0][3]);
            acc[0][4] = ffma2(d0, wC.x, acc[0][4]); acc[0][5] = ffma2(d0, wC.y, acc[0][5]);
            acc[0][6] = ffma2(d0, wD.x, acc[0][6]); acc[0][7] = ffma2(d0, wD.y, acc[0][7]);
            acc[1][0] = ffma2(d1, wA.x, acc[1][0]); acc[1][1] = ffma2(d1, wA.y, acc[1][1]);
            acc[1][2] = ffma2(d1, wB.x, acc[1][2]); acc[1][3] = ffma2(d1, wB.y, acc[1][3]);
            acc[1][4] = ffma2(d1, wC.x, acc[1][4]); acc[1][5] = ffma2(d1, wC.y, acc[1][5]);
            acc[1][6] = ffma2(d1, wD.x, acc[1][6]); acc[1][7] = ffma2(d1, wD.y, acc[1][7]);
            acc[2][0] = ffma2(d2, wA.x, acc[2][0]); acc[2][1] = ffma2(d2, wA.y, acc[2][1]);
            acc[2][2] = ffma2(d2, wB.x, acc[2][2]); acc[2][3] = ffma2(d2, wB.y, acc[2][3]);
            acc[2][4] = ffma2(d2, wC.x, acc[2][4]); acc[2][5] = ffma2(d2, wC.y, acc[2][5]);
            acc[2][6] = ffma2(d2, wD.x, acc[2][6]); acc[2][7] = ffma2(d2, wD.y, acc[2][7]);
            acc[3][0] = ffma2(d3, wA.x, acc[3][0]); acc[3][1] = ffma2(d3, wA.y, acc[3][1]);
            acc[3][2] = ffma2(d3, wB.x, acc[3][2]); acc[3][3] = ffma2(d3, wB.y, acc[3][3]);
            acc[3][4] = ffma2(d3, wC.x, acc[3][4]); acc[3][5] = ffma2(d3, wC.y, acc[3][5]);
            acc[3][6] = ffma2(d3, wD.x, acc[3][6]); acc[3][7] = ffma2(d3, wD.y, acc[3][7]);
        }
    }

#pragma unroll
    for (int r = 0; r < ROWS; r++)
#pragma unroll
        for (int p = 0; p < 8; p++) acc[r][p] = relu2(acc[r][p]);

    // ---- GEMM2 in QUARTERS (4 q-values = 2 pairs live per row) ----
#pragma unroll
    for (int qt = 0; qt < 4; qt++) {
        ull a2[ROWS][2];
        {
            const ull bp0 = *reinterpret_cast<const ull*>(&cP.bb[4 * qt + 0]);
            const ull bp1 = *reinterpret_cast<const ull*>(&cP.bb[4 * qt + 2]);
#pragma unroll
            for (int r = 0; r < ROWS; r++) { a2[r][0] = bp0; a2[r][1] = bp1; }
        }
#pragma unroll
        for (int o = 0; o < C; o++) {
            // one LDC.128: 4 q-weights (2 pairs) for this o, this quarter
            const ulonglong2 w = *reinterpret_cast<const ulonglong2*>(&cP.WbT[o * C + 4 * qt]);
#pragma unroll
            for (int r = 0; r < ROWS; r++) {
                float hlo, hhi;
                unpack2(acc[r][o >> 1], hlo, hhi);
                const float hs = (o & 1) ? hhi : hlo;
                const ull hd = pack2(hs, hs);
                a2[r][0] = ffma2(hd, w.x, a2[r][0]);
                a2[r][1] = ffma2(hd, w.y, a2[r][1]);
            }
        }
#pragma unroll
        for (int r = 0; r < ROWS; r++) {
            float v0, v1, v2, v3;
            unpack2(a2[r][0], v0, v1);
            unpack2(a2[r][1], v2, v3);
            sT[sw(16 * tid + r * 4 + qt)] = make_float4(v0, v1, v2, v3);
        }
    }
    __syncthreads();

    // 3) coalesced store from swizzled smem
    {
        float4* go4 = reinterpret_cast<float4*>(out + tileBase * C);
#pragma unroll
        for (int k = 0; k < 16; k++) {
            const int L = k * TPB + tid;
            go4[L] = sT[sw(L)];
        }
    }
}

extern "C" void kernel_launch(void* const* d_in, const int* in_sizes, int n_in,
                              void* d_out, int out_size)
{
    // metadata order: features, points, nuv, Wt, bt, Wa, ba, Wb, bb, ranges
    const float* feat = (const float*)d_in[0];
    const float* Wt   = (const float*)d_in[3];
    const float* bt   = (const float*)d_in[4];
    const float* Wa   = (const float*)d_in[5];
    const float* ba   = (const float*)d_in[6];
    const float* Wb   = (const float*)d_in[7];
    const float* bb   = (const float*)d_in[8];
    float* out = (float*)d_out;

    const long long n = (long long)in_sizes[0] / C;
    const int blocks = (int)((n + TILE_ROWS - 1) / TILE_ROWS);

    fold_kernel<<<1, 256>>>(Wt, bt, Wa, ba, Wb, bb);

    void* stage_ptr = nullptr;
    cudaGetSymbolAddress(&stage_ptr, gStage);
    cudaMemcpyToSymbolAsync(cP, stage_ptr, sizeof(FoldedParams), 0,
                            cudaMemcpyDeviceToDevice, 0);

    dmasif_fused_kernel<<<blocks, TPB>>>(feat, out, n);
}

// round 17
// speedup vs baseline: 1.1929x; 1.1929x over previous
#include <cuda_runtime.h>
#include <cuda_bf16.h>
#include <cstdint>

typedef unsigned long long ull;

// ---------------- f32x2 packed helpers (Blackwell) ----------------
__device__ __forceinline__ ull ffma2(ull a, ull b, ull c) {
    ull d;
    asm("fma.rn.f32x2 %0, %1, %2, %3;" : "=l"(d) : "l"(a), "l"(b), "l"(c));
    return d;
}
__device__ __forceinline__ ull pack2(float lo, float hi) {
    ull r;
    asm("mov.b64 %0, {%1, %2};" : "=l"(r) : "f"(lo), "f"(hi));
    return r;
}
__device__ __forceinline__ void unpack2(ull v, float& lo, float& hi) {
    asm("mov.b64 {%0, %1}, %2;" : "=f"(lo), "=f"(hi) : "l"(v));
}
__device__ __forceinline__ ull relu2(ull v) {
    float lo, hi;
    unpack2(v, lo, hi);
    return pack2(fmaxf(lo, 0.0f), fmaxf(hi, 0.0f));
}

static constexpr int C = 16;
static constexpr int TPB = 128;               // 4 warps; each warp owns 64 rows
static constexpr int ROWS = 2;                // rows per thread
static constexpr int TILE_ROWS = TPB * ROWS;  // 256
static constexpr int TILE_F4 = TILE_ROWS * 4; // 1024 float4 = 16KB

// Swizzle on float4 index: XOR low 3 bits with bits [4:7).
// Same address pattern as the measured-good R13 kernel.
__device__ __forceinline__ int sw(int L) { return L ^ ((L >> 4) & 7); }

// Folded parameters in __constant__ -> weight reads on the constant port.
struct FoldedParams {
    float WcT[C * C];   // [i*16 + o]   Wc^T, o contiguous (pairs adjacent)
    float WbT[C * C];   // [o*16 + q]   Wb^T, q contiguous
    float bc[C];        // folded bias: Wa@bt + ba
    float bb[C];
};

__device__ FoldedParams gStage;
__constant__ __align__(16) FoldedParams cP;

__global__ void fold_kernel(const float* __restrict__ Wt,
                            const float* __restrict__ bt,
                            const float* __restrict__ Wa,
                            const float* __restrict__ ba,
                            const float* __restrict__ Wb,
                            const float* __restrict__ bb)
{
    const int t = threadIdx.x;           // 256 threads
    const int o = t & 15;
    const int i = t >> 4;
    float acc = 0.0f;
#pragma unroll
    for (int m = 0; m < C; m++)
        acc += Wa[o * C + m] * Wt[m * C + i];
    gStage.WcT[i * C + o] = acc;
    gStage.WbT[t] = Wb[(t & 15) * C + (t >> 4)];
    if (t < C) {
        float b = ba[t];
#pragma unroll
        for (int m = 0; m < C; m++)
            b += Wa[t * C + m] * bt[m];
        gStage.bc[t] = b;
        gStage.bb[t] = bb[t];
    }
}

__global__ __launch_bounds__(TPB, 6)
void dmasif_fused_kernel(const float* __restrict__ feat,
                         float* __restrict__ out,
                         long long n)
{
    __shared__ float4 sT[TILE_F4];    // 16KB; each warp uses only its 4KB slice

    const int tid  = threadIdx.x;
    const int wrp  = tid >> 5;        // warp id (0..3)
    const int lane = tid & 31;
    const long long tileBase = (long long)blockIdx.x * TILE_ROWS;
    const bool fullTile = (tileBase + TILE_ROWS <= n);

    if (!fullTile) {
        // ---------- partial-tile path (last block only) ----------
        const long long base = tileBase + (long long)tid * ROWS;
        if (base >= n) return;
        for (int r = 0; r < ROWS; r++) {
            const long long row = base + r;
            if (row >= n) break;
            float h[C];
#pragma unroll
            for (int q = 0; q < C; q++) {
                float a = cP.bc[q];
                for (int i = 0; i < C; i++)
                    a += feat[row * C + i] * cP.WcT[i * C + q];
                h[q] = fmaxf(a, 0.0f);
            }
#pragma unroll
            for (int q = 0; q < C; q++) {
                float a = cP.bb[q];
                for (int o = 0; o < C; o++)
                    a += h[o] * cP.WbT[o * C + q];
                out[row * C + q] = a;
            }
        }
        return;
    }

    // ================= full tile — WARP-LOCAL staging =================
    // Warp w owns rows [64w, 64w+64) of the tile = float4 range [256w, 256w+256).
    const int wbase = 256 * wrp;

    // 1) warp-coalesced load -> swizzled smem (8 x 512B per warp)
    {
        const float4* gf4 = reinterpret_cast<const float4*>(feat + tileBase * C);
#pragma unroll
        for (int k = 0; k < 8; k++) {
            const int L = wbase + k * 32 + lane;
            sT[sw(L)] = gf4[L];
        }
    }
    __syncwarp();

    // ---- GEMM1 + ReLU: acc[r][p] = (h[r][2p], h[r][2p+1]) ----
    ull acc[ROWS][8];
#pragma unroll
    for (int p = 0; p < 8; p++) {
        const ull bp = *reinterpret_cast<const ull*>(&cP.bc[2 * p]);
#pragma unroll
        for (int r = 0; r < ROWS; r++) acc[r][p] = bp;
    }

#pragma unroll
    for (int ic = 0; ic < 4; ic++) {
        const float4 g0 = sT[sw(8 * tid + 0 * 4 + ic)];
        const float4 g1 = sT[sw(8 * tid + 1 * 4 + ic)];
        float e0v[4] = {g0.x, g0.y, g0.z, g0.w};
        float e1v[4] = {g1.x, g1.y, g1.z, g1.w};
#pragma unroll
        for (int ii = 0; ii < 4; ii++) {
            const int i = ic * 4 + ii;
            const ulonglong2 wA = *reinterpret_cast<const ulonglong2*>(&cP.WcT[i * C + 0]);
            const ulonglong2 wB = *reinterpret_cast<const ulonglong2*>(&cP.WcT[i * C + 4]);
            const ulonglong2 wC = *reinterpret_cast<const ulonglong2*>(&cP.WcT[i * C + 8]);
            const ulonglong2 wD = *reinterpret_cast<const ulonglong2*>(&cP.WcT[i * C + 12]);
            const ull d0 = pack2(e0v[ii], e0v[ii]);
            const ull d1 = pack2(e1v[ii], e1v[ii]);
            acc[0][0] = ffma2(d0, wA.x, acc[0][0]); acc[0][1] = ffma2(d0, wA.y, acc[0][1]);
            acc[0][2] = ffma2(d0, wB.x, acc[0][2]); acc[0][3] = ffma2(d0, wB.y, acc[0][3]);
            acc[0][4] = ffma2(d0, wC.x, acc[0][4]); acc[0][5] = ffma2(d0, wC.y, acc[0][5]);
            acc[0][6] = ffma2(d0, wD.x, acc[0][6]); acc[0][7] = ffma2(d0, wD.y, acc[0][7]);
            acc[1][0] = ffma2(d1, wA.x, acc[1][0]); acc[1][1] = ffma2(d1, wA.y, acc[1][1]);
            acc[1][2] = ffma2(d1, wB.x, acc[1][2]); acc[1][3] = ffma2(d1, wB.y, acc[1][3]);
            acc[1][4] = ffma2(d1, wC.x, acc[1][4]); acc[1][5] = ffma2(d1, wC.y, acc[1][5]);
            acc[1][6] = ffma2(d1, wD.x, acc[1][6]); acc[1][7] = ffma2(d1, wD.y, acc[1][7]);
        }
    }

#pragma unroll
    for (int r = 0; r < ROWS; r++)
#pragma unroll
        for (int p = 0; p < 8; p++) acc[r][p] = relu2(acc[r][p]);

    // ---- GEMM2 in halves; h unpacked once per PAIR (not per o) ----
#pragma unroll
    for (int half = 0; half < 2; half++) {
        ull a2[ROWS][4];
#pragma unroll
        for (int pp = 0; pp < 4; pp++) {
            const ull bp = *reinterpret_cast<const ull*>(&cP.bb[half * 8 + 2 * pp]);
#pragma unroll
            for (int r = 0; r < ROWS; r++) a2[r][pp] = bp;
        }
#pragma unroll
        for (int p = 0; p < 8; p++) {           // h channel-pair (o=2p, 2p+1)
            float h0lo, h0hi, h1lo, h1hi;
            unpack2(acc[0][p], h0lo, h0hi);
            unpack2(acc[1][p], h1lo, h1hi);
            {   // o = 2p
                const int o = 2 * p;
                const ulonglong2 wA = *reinterpret_cast<const ulonglong2*>(&cP.WbT[o * C + half * 8 + 0]);
                const ulonglong2 wB = *reinterpret_cast<const ulonglong2*>(&cP.WbT[o * C + half * 8 + 4]);
                const ull hd0 = pack2(h0lo, h0lo);
                const ull hd1 = pack2(h1lo, h1lo);
                a2[0][0] = ffma2(hd0, wA.x, a2[0][0]); a2[0][1] = ffma2(hd0, wA.y, a2[0][1]);
                a2[0][2] = ffma2(hd0, wB.x, a2[0][2]); a2[0][3] = ffma2(hd0, wB.y, a2[0][3]);
                a2[1][0] = ffma2(hd1, wA.x, a2[1][0]); a2[1][1] = ffma2(hd1, wA.y, a2[1][1]);
                a2[1][2] = ffma2(hd1, wB.x, a2[1][2]); a2[1][3] = ffma2(hd1, wB.y, a2[1][3]);
            }
            {   // o = 2p+1
                const int o = 2 * p + 1;
                const ulonglong2 wA = *reinterpret_cast<const ulonglong2*>(&cP.WbT[o * C + half * 8 + 0]);
                const ulonglong2 wB = *reinterpret_cast<const ulonglong2*>(&cP.WbT[o * C + half * 8 + 4]);
                const ull hd0 = pack2(h0hi, h0hi);
                const ull hd1 = pack2(h1hi, h1hi);
                a2[0][0] = ffma2(hd0, wA.x, a2[0][0]); a2[0][1] = ffma2(hd0, wA.y, a2[0][1]);
                a2[0][2] = ffma2(hd0, wB.x, a2[0][2]); a2[0][3] = ffma2(hd0, wB.y, a2[0][3]);
                a2[1][0] = ffma2(hd1, wA.x, a2[1][0]); a2[1][1] = ffma2(hd1, wA.y, a2[1][1]);
                a2[1][2] = ffma2(hd1, wB.x, a2[1][2]); a2[1][3] = ffma2(hd1, wB.y, a2[1][3]);
            }
        }
#pragma unroll
        for (int r = 0; r < ROWS; r++) {
            float v0, v1, v2, v3, v4, v5, v6, v7;
            unpack2(a2[r][0], v0, v1);
            unpack2(a2[r][1], v2, v3);
            unpack2(a2[r][2], v4, v5);
            unpack2(a2[r][3], v6, v7);
            sT[sw(8 * tid + r * 4 + half * 2 + 0)] = make_float4(v0, v1, v2, v3);
            sT[sw(8 * tid + r * 4 + half * 2 + 1)] = make_float4(v4, v5, v6, v7);
        }
    }
    __syncwarp();

    // 3) warp-coalesced store from swizzled smem
    {
        float4* go4 = reinterpret_cast<float4*>(out + tileBase * C);
#pragma unroll
        for (int k = 0; k < 8; k++) {
            const int L = wbase + k * 32 + lane;
            go4[L] = sT[sw(L)];
        }
    }
}

extern "C" void kernel_launch(void* const* d_in, const int* in_sizes, int n_in,
                              void* d_out, int out_size)
{
    // metadata order: features, points, nuv, Wt, bt, Wa, ba, Wb, bb, ranges
    const float* feat = (const float*)d_in[0];
    const float* Wt   = (const float*)d_in[3];
    const float* bt   = (const float*)d_in[4];
    const float* Wa   = (const float*)d_in[5];
    const float* ba   = (const float*)d_in[6];
    const float* Wb   = (const float*)d_in[7];
    const float* bb   = (const float*)d_in[8];
    float* out = (float*)d_out;

    const long long n = (long long)in_sizes[0] / C;
    const int blocks = (int)((n + TILE_ROWS - 1) / TILE_ROWS);

    fold_kernel<<<1, 256>>>(Wt, bt, Wa, ba, Wb, bb);

    void* stage_ptr = nullptr;
    cudaGetSymbolAddress(&stage_ptr, gStage);
    cudaMemcpyToSymbolAsync(cP, stage_ptr, sizeof(FoldedParams), 0,
                            cudaMemcpyDeviceToDevice, 0);

    dmasif_fused_kernel<<<blocks, TPB>>>(feat, out, n);
}